// round 15
// baseline (speedup 1.0000x reference)
#include <cuda_runtime.h>
#include <cuda_fp16.h>
#include <cstdint>

// out = x @ V @ diag(S) @ U^T + bias  via mma.sync m16n8k16 fp16 (f32 accum).
// prep_all: one fused kernel (x->h, U->h, Vt=(V*S)^T->h), 2 float4/thread.
// fused_static: ONE launch, grid=2560; bid<512 -> GEMM1 tile, else GEMM2 tile
// gated on g_mdone[m]. gemm_tile constexpr-specialized per GEMM.
// NEW: co-resident CTAs get opposite K-loop phases (rotated k-chunk order) so
// their per-iter barriers interleave instead of coinciding (lockstep-barrier fix).

#define CTA_M 128
#define CTA_N 128
#define CTA_K 64
#define NSTAGES 3

static constexpr int A_BYTES = CTA_M * CTA_K * 2;          // 16384
static constexpr int B_BYTES = CTA_N * CTA_K * 2;          // 16384
static constexpr int STAGE_BYTES = A_BYTES + B_BYTES;      // 32768
static constexpr int SMEM_TOTAL = NSTAGES * STAGE_BYTES;   // 98304

static constexpr int G1_TILES = 512;    // 64 m x 8 n
static constexpr int G2_TILES = 2048;   // 64 m x 32 n
static constexpr int N_TILES = G1_TILES + G2_TILES;

// prep block ranges (2 float4 per thread for the convert parts)
static constexpr int XBLKS = (8192 * 4096 / 8) / 256;   // 16384
static constexpr int UBLKS = (4096 * 1024 / 8) / 256;   // 2048
static constexpr int VBLKS = 128 * 32;                  // 4096
static constexpr int PREP_BLKS = XBLKS + UBLKS + VBLKS;

// Scratch (allocation-free rule: __device__ globals)
__device__ __align__(128) __half g_xh[8192 * 4096];
__device__ __align__(128) __half g_Vth[1024 * 4096];
__device__ __align__(128) __half g_Uh[4096 * 1024];
__device__ __align__(128) __half g_Ts[8192 * 1024];
__device__ unsigned g_mdone[64];

__device__ __forceinline__ uint32_t smem_u32(const void* p) {
    uint32_t a;
    asm("{ .reg .u64 t; cvta.to.shared.u64 t, %1; cvt.u32.u64 %0, t; }" : "=r"(a) : "l"(p));
    return a;
}
__device__ __forceinline__ void cp16(uint32_t dst, const void* src) {
    asm volatile("cp.async.cg.shared.global [%0], [%1], 16;" :: "r"(dst), "l"(src));
}
__device__ __forceinline__ void cp_commit() {
    asm volatile("cp.async.commit_group;" ::: "memory");
}
template <int N>
__device__ __forceinline__ void cp_wait() {
    asm volatile("cp.async.wait_group %0;" :: "n"(N) : "memory");
}
__device__ __forceinline__ void ldsm4(uint32_t* r, uint32_t addr) {
    asm volatile("ldmatrix.sync.aligned.m8n8.x4.shared.b16 {%0,%1,%2,%3}, [%4];"
                 : "=r"(r[0]), "=r"(r[1]), "=r"(r[2]), "=r"(r[3]) : "r"(addr));
}
__device__ __forceinline__ void mma_f16(float* d,
                                        const uint32_t* a, uint32_t b0, uint32_t b1) {
    asm volatile(
        "mma.sync.aligned.m16n8k16.row.col.f32.f16.f16.f32 "
        "{%0,%1,%2,%3}, {%4,%5,%6,%7}, {%8,%9}, {%0,%1,%2,%3};"
        : "+f"(d[0]), "+f"(d[1]), "+f"(d[2]), "+f"(d[3])
        : "r"(a[0]), "r"(a[1]), "r"(a[2]), "r"(a[3]), "r"(b0), "r"(b1));
}
__device__ __forceinline__ uint32_t h2pack(float a, float b) {
    __half2 h = __floats2half2_rn(a, b);
    return *reinterpret_cast<uint32_t*>(&h);
}
__device__ __forceinline__ uint32_t tile_addr(uint32_t base, int row, int chunk) {
    return base + row * 128 + ((chunk ^ (row & 7)) << 4);
}
__device__ __forceinline__ uint32_t frag_addr(uint32_t base, int base_row, int kt, int lane) {
    int r = base_row + (lane & 15);
    int chunk = kt * 2 + (lane >> 4);
    return tile_addr(base, r, chunk);
}

// ---------------- fused prep megakernel (2 float4 per thread) ----------------
__global__ __launch_bounds__(256) void prep_all(
    const float* __restrict__ x, const float* __restrict__ U,
    const float* __restrict__ V, const float* __restrict__ S,
    __half* __restrict__ xh, __half* __restrict__ Uh, __half* __restrict__ Vth)
{
    const int b = blockIdx.x;
    const int tid = threadIdx.x;
    if (b < XBLKS + UBLKS) {
        const float* in = (b < XBLKS) ? x : U;
        __half* out = (b < XBLKS) ? xh : Uh;
        size_t base = (size_t)(b < XBLKS ? b : b - XBLKS) * 512 + tid;
        float4 v0 = *reinterpret_cast<const float4*>(in + base * 4);
        float4 v1 = *reinterpret_cast<const float4*>(in + (base + 256) * 4);
        __half2 a0 = __floats2half2_rn(v0.x, v0.y);
        __half2 a1 = __floats2half2_rn(v0.z, v0.w);
        __half2 b0 = __floats2half2_rn(v1.x, v1.y);
        __half2 b1 = __floats2half2_rn(v1.z, v1.w);
        *reinterpret_cast<uint2*>(out + base * 4) =
            make_uint2(*(uint32_t*)&a0, *(uint32_t*)&a1);
        *reinterpret_cast<uint2*>(out + (base + 256) * 4) =
            make_uint2(*(uint32_t*)&b0, *(uint32_t*)&b1);
    } else {
        __shared__ float t[32][33];
        const int vb = b - XBLKS - UBLKS;
        const int k0 = (vb & 127) * 32;
        const int n0 = (vb >> 7) * 32;
        const int tx = tid & 31, ty = tid >> 5;
        #pragma unroll
        for (int r = ty; r < 32; r += 8)
            t[r][tx] = V[(size_t)(k0 + r) * 1024 + n0 + tx];
        __syncthreads();
        #pragma unroll
        for (int r = ty; r < 32; r += 8) {
            int n = n0 + r, k = k0 + tx;
            Vth[(size_t)n * 4096 + k] = __float2half_rn(t[tx][r] * S[n]);
        }
    }
}

// ---------------- GEMM tile, constexpr-specialized, K-phase rotated ----------
template <bool IS1>
__device__ __forceinline__ void gemm_tile(
    uint32_t sbase, int tid, int m, int n, int phase,
    const __half* __restrict__ A, const __half* __restrict__ B,
    const float* __restrict__ bias, __half* __restrict__ Ts, float* __restrict__ out)
{
    constexpr int K   = IS1 ? 4096 : 1024;
    constexpr int LDA = IS1 ? 4096 : 1024;
    constexpr int LDB = IS1 ? 4096 : 1024;
    constexpr int LDC = IS1 ? 1024 : 4096;
    constexpr int T = K / CTA_K;

    const int lane = tid & 31, wid = tid >> 5;
    const int wm = wid >> 2, wn = wid & 3;        // 2 x 4 warps, warp tile 64x32
    const int lrow = tid >> 3, lc = tid & 7;
    const int bm = m * CTA_M, bn = n * CTA_N;
    const int off = phase * (T / 2);              // rotated k-chunk order

    auto kof = [&](int j) {
        int t = j + off;
        if (t >= T) t -= T;
        return t * CTA_K;
    };

    auto load_stage = [&](int s, int k0) {
        uint32_t sa = sbase + s * STAGE_BYTES;
        uint32_t sb = sa + A_BYTES;
        const __half* gA = A + (size_t)bm * LDA + k0 + lc * 8;
        const __half* gB = B + (size_t)bn * LDB + k0 + lc * 8;
        #pragma unroll
        for (int j = 0; j < 4; j++) {
            int r = lrow + 32 * j;
            cp16(tile_addr(sa, r, lc), gA + (size_t)r * LDA);
        }
        #pragma unroll
        for (int j = 0; j < 4; j++) {
            int r = lrow + 32 * j;
            cp16(tile_addr(sb, r, lc), gB + (size_t)r * LDB);
        }
    };

    float acc[4][4][4];
    #pragma unroll
    for (int i = 0; i < 4; i++)
        #pragma unroll
        for (int j = 0; j < 4; j++)
            #pragma unroll
            for (int r = 0; r < 4; r++)
                acc[i][j][r] = 0.0f;

    load_stage(0, kof(0)); cp_commit();
    load_stage(1, kof(1)); cp_commit();

    for (int it = 0; it < T; ++it) {
        cp_wait<1>();
        __syncthreads();
        if (it + 2 < T) load_stage((it + 2) % NSTAGES, kof(it + 2));
        cp_commit();

        const int s = it % NSTAGES;
        const uint32_t sa = sbase + s * STAGE_BYTES;
        const uint32_t sb = sa + A_BYTES;

        #pragma unroll
        for (int kt = 0; kt < 4; kt++) {
            uint32_t af[4][4];
            uint32_t bf[2][4];
            #pragma unroll
            for (int mt = 0; mt < 4; mt++)
                ldsm4(af[mt], frag_addr(sa, wm * 64 + mt * 16, kt, lane));
            #pragma unroll
            for (int ng = 0; ng < 2; ng++)
                ldsm4(bf[ng], frag_addr(sb, wn * 32 + ng * 16, kt, lane));
            #pragma unroll
            for (int mt = 0; mt < 4; mt++) {
                #pragma unroll
                for (int ng = 0; ng < 2; ng++) {
                    mma_f16(acc[mt][2 * ng],     af[mt], bf[ng][0], bf[ng][2]);
                    mma_f16(acc[mt][2 * ng + 1], af[mt], bf[ng][1], bf[ng][3]);
                }
            }
        }
    }

    const int g = lane >> 2, tig = lane & 3;
    if (IS1) {
        #pragma unroll
        for (int mt = 0; mt < 4; mt++) {
            #pragma unroll
            for (int nt = 0; nt < 4; nt++) {
                int row = bm + wm * 64 + mt * 16 + g;
                int col = bn + wn * 32 + nt * 8 + tig * 2;
                *reinterpret_cast<uint32_t*>(Ts + (size_t)row * LDC + col) =
                    h2pack(acc[mt][nt][0], acc[mt][nt][1]);
                *reinterpret_cast<uint32_t*>(Ts + (size_t)(row + 8) * LDC + col) =
                    h2pack(acc[mt][nt][2], acc[mt][nt][3]);
            }
        }
        __threadfence();
        __syncthreads();
        if (tid == 0) atomicAdd(&g_mdone[m], 1u);
    } else {
        #pragma unroll
        for (int mt = 0; mt < 4; mt++) {
            #pragma unroll
            for (int nt = 0; nt < 4; nt++) {
                int row = bm + wm * 64 + mt * 16 + g;
                int col = bn + wn * 32 + nt * 8 + tig * 2;
                float2 b = *reinterpret_cast<const float2*>(bias + col);
                *reinterpret_cast<float2*>(out + (size_t)row * LDC + col) =
                    make_float2(acc[mt][nt][0] + b.x, acc[mt][nt][1] + b.y);
                *reinterpret_cast<float2*>(out + (size_t)(row + 8) * LDC + col) =
                    make_float2(acc[mt][nt][2] + b.x, acc[mt][nt][3] + b.y);
            }
        }
    }
}

// ---------------- static-fused GEMM: one tile per CTA ----------------
__global__ __launch_bounds__(256, 2) void fused_static(
    const __half* __restrict__ xh, const __half* __restrict__ Vth,
    const __half* __restrict__ Uh, const float* __restrict__ bias,
    __half* __restrict__ Ts, float* __restrict__ out)
{
    extern __shared__ char sm[];
    const uint32_t sbase = smem_u32(sm);
    const int tid = threadIdx.x;
    const int bid = blockIdx.x;

    // Anti-phase co-resident CTAs: linear wave fill puts bids b and b+148 on
    // the same SM (2 CTAs/SM, 296 slots) -> opposite phases for the K rotation.
    const int phase = ((bid % 296) >= 148) ? 1 : 0;

    if (bid < G1_TILES) {
        const int m = bid >> 3, n = bid & 7;
        gemm_tile<true>(sbase, tid, m, n, phase, xh, Vth, bias, Ts, out);
    } else {
        const int t2 = bid - G1_TILES;
        const int m = t2 >> 5, n = t2 & 31;
        if (tid == 0) {
            while (*((volatile unsigned*)&g_mdone[m]) < 8u) __nanosleep(128);
        }
        __syncthreads();
        __threadfence();   // acquire: order subsequent reads after the flag
        gemm_tile<false>(sbase, tid, m, n, phase, Ts, Uh, bias, Ts, out);
    }
}

extern "C" void kernel_launch(void* const* d_in, const int* in_sizes, int n_in,
                              void* d_out, int out_size)
{
    const float* x    = (const float*)d_in[0];   // [8192,4096]
    const float* U    = (const float*)d_in[1];   // [4096,1024]
    const float* S    = (const float*)d_in[2];   // [1024]
    const float* V    = (const float*)d_in[3];   // [4096,1024]
    const float* bias = (const float*)d_in[4];   // [4096]
    float* out = (float*)d_out;                  // [8192,4096]

    __half *xh, *Vth, *Uh, *Ts;
    cudaGetSymbolAddress((void**)&xh, g_xh);
    cudaGetSymbolAddress((void**)&Vth, g_Vth);
    cudaGetSymbolAddress((void**)&Uh, g_Uh);
    cudaGetSymbolAddress((void**)&Ts, g_Ts);

    void* mdone;
    cudaGetSymbolAddress(&mdone, g_mdone);
    cudaMemsetAsync(mdone, 0, 64 * sizeof(unsigned));

    cudaFuncSetAttribute(fused_static,
                         cudaFuncAttributeMaxDynamicSharedMemorySize, SMEM_TOTAL);

    // fused prep: x->h, U->h, Vt=(V*S)^T->h
    prep_all<<<PREP_BLKS, 256>>>(x, U, V, S, xh, Uh, Vth);

    // one static-fused launch: 512 GEMM1 tiles then 2048 GEMM2 tiles
    fused_static<<<N_TILES, 256, SMEM_TOTAL>>>(xh, Vth, Uh, bias, Ts, out);
}

// round 16
// speedup vs baseline: 1.0152x; 1.0152x over previous
#include <cuda_runtime.h>
#include <cuda_fp16.h>
#include <cstdint>

// out = x @ V @ diag(S) @ U^T + bias  via mma.sync m16n8k16 fp16 (f32 accum).
// prep_all: one fused kernel (x->h, U->h, Vt=(V*S)^T->h), 2 float4/thread.
// fused_static: ONE launch, grid=2560; bid<512 -> GEMM1 tile, else GEMM2 tile
// gated on g_mdone[m]. gemm_tile constexpr-specialized per GEMM.
// NEW vs R14: 128-thread CTAs, 4 warps of 64x64 (halves LSU ops per MMA);
// 2 CTAs/SM still (128thr allows 255 regs/thread). 3-stage cp.async unchanged.

#define CTA_M 128
#define CTA_N 128
#define CTA_K 64
#define NSTAGES 3

static constexpr int A_BYTES = CTA_M * CTA_K * 2;          // 16384
static constexpr int B_BYTES = CTA_N * CTA_K * 2;          // 16384
static constexpr int STAGE_BYTES = A_BYTES + B_BYTES;      // 32768
static constexpr int SMEM_TOTAL = NSTAGES * STAGE_BYTES;   // 98304

static constexpr int G1_TILES = 512;    // 64 m x 8 n
static constexpr int G2_TILES = 2048;   // 64 m x 32 n
static constexpr int N_TILES = G1_TILES + G2_TILES;

// prep block ranges (2 float4 per thread for the convert parts)
static constexpr int XBLKS = (8192 * 4096 / 8) / 256;   // 16384
static constexpr int UBLKS = (4096 * 1024 / 8) / 256;   // 2048
static constexpr int VBLKS = 128 * 32;                  // 4096
static constexpr int PREP_BLKS = XBLKS + UBLKS + VBLKS;

// Scratch (allocation-free rule: __device__ globals)
__device__ __align__(128) __half g_xh[8192 * 4096];
__device__ __align__(128) __half g_Vth[1024 * 4096];
__device__ __align__(128) __half g_Uh[4096 * 1024];
__device__ __align__(128) __half g_Ts[8192 * 1024];
__device__ unsigned g_mdone[64];

__device__ __forceinline__ uint32_t smem_u32(const void* p) {
    uint32_t a;
    asm("{ .reg .u64 t; cvta.to.shared.u64 t, %1; cvt.u32.u64 %0, t; }" : "=r"(a) : "l"(p));
    return a;
}
__device__ __forceinline__ void cp16(uint32_t dst, const void* src) {
    asm volatile("cp.async.cg.shared.global [%0], [%1], 16;" :: "r"(dst), "l"(src));
}
__device__ __forceinline__ void cp_commit() {
    asm volatile("cp.async.commit_group;" ::: "memory");
}
template <int N>
__device__ __forceinline__ void cp_wait() {
    asm volatile("cp.async.wait_group %0;" :: "n"(N) : "memory");
}
__device__ __forceinline__ void ldsm4(uint32_t* r, uint32_t addr) {
    asm volatile("ldmatrix.sync.aligned.m8n8.x4.shared.b16 {%0,%1,%2,%3}, [%4];"
                 : "=r"(r[0]), "=r"(r[1]), "=r"(r[2]), "=r"(r[3]) : "r"(addr));
}
__device__ __forceinline__ void mma_f16(float* d,
                                        const uint32_t* a, uint32_t b0, uint32_t b1) {
    asm volatile(
        "mma.sync.aligned.m16n8k16.row.col.f32.f16.f16.f32 "
        "{%0,%1,%2,%3}, {%4,%5,%6,%7}, {%8,%9}, {%0,%1,%2,%3};"
        : "+f"(d[0]), "+f"(d[1]), "+f"(d[2]), "+f"(d[3])
        : "r"(a[0]), "r"(a[1]), "r"(a[2]), "r"(a[3]), "r"(b0), "r"(b1));
}
__device__ __forceinline__ uint32_t h2pack(float a, float b) {
    __half2 h = __floats2half2_rn(a, b);
    return *reinterpret_cast<uint32_t*>(&h);
}
__device__ __forceinline__ uint32_t tile_addr(uint32_t base, int row, int chunk) {
    return base + row * 128 + ((chunk ^ (row & 7)) << 4);
}
__device__ __forceinline__ uint32_t frag_addr(uint32_t base, int base_row, int kt, int lane) {
    int r = base_row + (lane & 15);
    int chunk = kt * 2 + (lane >> 4);
    return tile_addr(base, r, chunk);
}

// ---------------- fused prep megakernel (2 float4 per thread) ----------------
__global__ __launch_bounds__(256) void prep_all(
    const float* __restrict__ x, const float* __restrict__ U,
    const float* __restrict__ V, const float* __restrict__ S,
    __half* __restrict__ xh, __half* __restrict__ Uh, __half* __restrict__ Vth)
{
    const int b = blockIdx.x;
    const int tid = threadIdx.x;
    if (b < XBLKS + UBLKS) {
        const float* in = (b < XBLKS) ? x : U;
        __half* out = (b < XBLKS) ? xh : Uh;
        size_t base = (size_t)(b < XBLKS ? b : b - XBLKS) * 512 + tid;
        float4 v0 = *reinterpret_cast<const float4*>(in + base * 4);
        float4 v1 = *reinterpret_cast<const float4*>(in + (base + 256) * 4);
        __half2 a0 = __floats2half2_rn(v0.x, v0.y);
        __half2 a1 = __floats2half2_rn(v0.z, v0.w);
        __half2 b0 = __floats2half2_rn(v1.x, v1.y);
        __half2 b1 = __floats2half2_rn(v1.z, v1.w);
        *reinterpret_cast<uint2*>(out + base * 4) =
            make_uint2(*(uint32_t*)&a0, *(uint32_t*)&a1);
        *reinterpret_cast<uint2*>(out + (base + 256) * 4) =
            make_uint2(*(uint32_t*)&b0, *(uint32_t*)&b1);
    } else {
        __shared__ float t[32][33];
        const int vb = b - XBLKS - UBLKS;
        const int k0 = (vb & 127) * 32;
        const int n0 = (vb >> 7) * 32;
        const int tx = tid & 31, ty = tid >> 5;
        #pragma unroll
        for (int r = ty; r < 32; r += 8)
            t[r][tx] = V[(size_t)(k0 + r) * 1024 + n0 + tx];
        __syncthreads();
        #pragma unroll
        for (int r = ty; r < 32; r += 8) {
            int n = n0 + r, k = k0 + tx;
            Vth[(size_t)n * 4096 + k] = __float2half_rn(t[tx][r] * S[n]);
        }
    }
}

// ---------------- GEMM tile: 128 threads, 4 warps of 64x64 -------------------
template <bool IS1>
__device__ __forceinline__ void gemm_tile(
    uint32_t sbase, int tid, int m, int n,
    const __half* __restrict__ A, const __half* __restrict__ B,
    const float* __restrict__ bias, __half* __restrict__ Ts, float* __restrict__ out)
{
    constexpr int K   = IS1 ? 4096 : 1024;
    constexpr int LDA = IS1 ? 4096 : 1024;
    constexpr int LDB = IS1 ? 4096 : 1024;
    constexpr int LDC = IS1 ? 1024 : 4096;
    constexpr int T = K / CTA_K;

    const int lane = tid & 31, wid = tid >> 5;
    const int wm = wid >> 1, wn = wid & 1;        // 2 x 2 warps, warp tile 64x64
    const int lrow = tid >> 3, lc = tid & 7;      // lrow 0..15
    const int bm = m * CTA_M, bn = n * CTA_N;

    auto load_stage = [&](int s, int k0) {
        uint32_t sa = sbase + s * STAGE_BYTES;
        uint32_t sb = sa + A_BYTES;
        const __half* gA = A + (size_t)bm * LDA + k0 + lc * 8;
        const __half* gB = B + (size_t)bn * LDB + k0 + lc * 8;
        #pragma unroll
        for (int j = 0; j < 8; j++) {
            int r = lrow + 16 * j;
            cp16(tile_addr(sa, r, lc), gA + (size_t)r * LDA);
        }
        #pragma unroll
        for (int j = 0; j < 8; j++) {
            int r = lrow + 16 * j;
            cp16(tile_addr(sb, r, lc), gB + (size_t)r * LDB);
        }
    };

    float acc[4][8][4];
    #pragma unroll
    for (int i = 0; i < 4; i++)
        #pragma unroll
        for (int j = 0; j < 8; j++)
            #pragma unroll
            for (int r = 0; r < 4; r++)
                acc[i][j][r] = 0.0f;

    load_stage(0, 0); cp_commit();
    load_stage(1, CTA_K); cp_commit();

    for (int it = 0; it < T; ++it) {
        cp_wait<1>();
        __syncthreads();
        if (it + 2 < T) load_stage((it + 2) % NSTAGES, (it + 2) * CTA_K);
        cp_commit();

        const int s = it % NSTAGES;
        const uint32_t sa = sbase + s * STAGE_BYTES;
        const uint32_t sb = sa + A_BYTES;

        #pragma unroll
        for (int kt = 0; kt < 4; kt++) {
            uint32_t af[4][4];
            #pragma unroll
            for (int mt = 0; mt < 4; mt++)
                ldsm4(af[mt], frag_addr(sa, wm * 64 + mt * 16, kt, lane));
            #pragma unroll
            for (int ng = 0; ng < 4; ng++) {
                uint32_t bf[4];
                ldsm4(bf, frag_addr(sb, wn * 64 + ng * 16, kt, lane));
                #pragma unroll
                for (int mt = 0; mt < 4; mt++) {
                    mma_f16(acc[mt][2 * ng],     af[mt], bf[0], bf[2]);
                    mma_f16(acc[mt][2 * ng + 1], af[mt], bf[1], bf[3]);
                }
            }
        }
    }

    const int g = lane >> 2, tig = lane & 3;
    if (IS1) {
        #pragma unroll
        for (int mt = 0; mt < 4; mt++) {
            #pragma unroll
            for (int nt = 0; nt < 8; nt++) {
                int row = bm + wm * 64 + mt * 16 + g;
                int col = bn + wn * 64 + nt * 8 + tig * 2;
                *reinterpret_cast<uint32_t*>(Ts + (size_t)row * LDC + col) =
                    h2pack(acc[mt][nt][0], acc[mt][nt][1]);
                *reinterpret_cast<uint32_t*>(Ts + (size_t)(row + 8) * LDC + col) =
                    h2pack(acc[mt][nt][2], acc[mt][nt][3]);
            }
        }
        __threadfence();
        __syncthreads();
        if (tid == 0) atomicAdd(&g_mdone[m], 1u);
    } else {
        #pragma unroll
        for (int mt = 0; mt < 4; mt++) {
            #pragma unroll
            for (int nt = 0; nt < 8; nt++) {
                int row = bm + wm * 64 + mt * 16 + g;
                int col = bn + wn * 64 + nt * 8 + tig * 2;
                float2 b = *reinterpret_cast<const float2*>(bias + col);
                *reinterpret_cast<float2*>(out + (size_t)row * LDC + col) =
                    make_float2(acc[mt][nt][0] + b.x, acc[mt][nt][1] + b.y);
                *reinterpret_cast<float2*>(out + (size_t)(row + 8) * LDC + col) =
                    make_float2(acc[mt][nt][2] + b.x, acc[mt][nt][3] + b.y);
            }
        }
    }
}

// ---------------- static-fused GEMM: one tile per CTA ----------------
__global__ __launch_bounds__(128, 2) void fused_static(
    const __half* __restrict__ xh, const __half* __restrict__ Vth,
    const __half* __restrict__ Uh, const float* __restrict__ bias,
    __half* __restrict__ Ts, float* __restrict__ out)
{
    extern __shared__ char sm[];
    const uint32_t sbase = smem_u32(sm);
    const int tid = threadIdx.x;
    const int bid = blockIdx.x;

    if (bid < G1_TILES) {
        const int m = bid >> 3, n = bid & 7;
        gemm_tile<true>(sbase, tid, m, n, xh, Vth, bias, Ts, out);
    } else {
        const int t2 = bid - G1_TILES;
        const int m = t2 >> 5, n = t2 & 31;
        if (tid == 0) {
            while (*((volatile unsigned*)&g_mdone[m]) < 8u) __nanosleep(128);
        }
        __syncthreads();
        __threadfence();   // acquire: order subsequent reads after the flag
        gemm_tile<false>(sbase, tid, m, n, Ts, Uh, bias, Ts, out);
    }
}

extern "C" void kernel_launch(void* const* d_in, const int* in_sizes, int n_in,
                              void* d_out, int out_size)
{
    const float* x    = (const float*)d_in[0];   // [8192,4096]
    const float* U    = (const float*)d_in[1];   // [4096,1024]
    const float* S    = (const float*)d_in[2];   // [1024]
    const float* V    = (const float*)d_in[3];   // [4096,1024]
    const float* bias = (const float*)d_in[4];   // [4096]
    float* out = (float*)d_out;                  // [8192,4096]

    __half *xh, *Vth, *Uh, *Ts;
    cudaGetSymbolAddress((void**)&xh, g_xh);
    cudaGetSymbolAddress((void**)&Vth, g_Vth);
    cudaGetSymbolAddress((void**)&Uh, g_Uh);
    cudaGetSymbolAddress((void**)&Ts, g_Ts);

    void* mdone;
    cudaGetSymbolAddress(&mdone, g_mdone);
    cudaMemsetAsync(mdone, 0, 64 * sizeof(unsigned));

    cudaFuncSetAttribute(fused_static,
                         cudaFuncAttributeMaxDynamicSharedMemorySize, SMEM_TOTAL);

    // fused prep: x->h, U->h, Vt=(V*S)^T->h
    prep_all<<<PREP_BLKS, 256>>>(x, U, V, S, xh, Uh, Vth);

    // one static-fused launch: 512 GEMM1 tiles then 2048 GEMM2 tiles
    fused_static<<<N_TILES, 128, SMEM_TOTAL>>>(xh, Vth, Uh, bias, Ts, out);
}